// round 13
// baseline (speedup 1.0000x reference)
#include <cuda_runtime.h>
#include <cuda_bf16.h>

#define NPTS 8192
#define MAXN 128
#define NCX 32              // fine x bins; cutoff 0.125 = exactly 4 bins
#define NCY 8
#define NCZ 8
#define NCELLS (NCZ * NCY * NCX)   // 2048
#define CUT2 0.015625f      // 0.125^2, exact in fp32
#define WPB 8               // warps per block; 2 rows per warp
#define TPB (WPB * 32)      // 256
#define NB (NPTS / (2 * WPB))  // 512 blocks, co-resident (<= 148*4)

// Scratch (no allocations allowed). Zero-initialized at module load.
__device__ int      g_count[NCELLS];   // histogram; reset in-kernel each run
__device__ float4   g_spos[NPTS];      // cell-sorted {x,y,z, idx-as-float-bits}
__device__ unsigned g_bar;             // monotonic grid-barrier ticket

__device__ __forceinline__ int binf(float v, int n) {
    // v in [0,1): v*n (n power of 2) is an exact exponent shift; trunc==floor
    int c = (int)(v * (float)n);
    return c < 0 ? 0 : (c > n - 1 ? n - 1 : c);
}

// Grid barrier for a co-resident grid of nb blocks. Monotonic ticket ->
// counter is a multiple of nb at rest -> safe across graph replays.
__device__ __forceinline__ void grid_barrier(unsigned nb) {
    __syncthreads();
    if (threadIdx.x == 0) {
        __threadfence();
        const unsigned ticket = atomicAdd(&g_bar, 1u);
        const unsigned target = (ticket / nb + 1u) * nb;
        volatile unsigned* p = &g_bar;
        while (*p < target) { __nanosleep(32); }
    }
    __syncthreads();
}

// Build the 9-segment (3x3 in z,y) window with fine-x range [x0, x1].
__device__ __forceinline__ void make_window(const int* __restrict__ s_start,
                                            int x0, int x1, int cy, int cz,
                                            int o[10], int dlt[9]) {
    o[0] = 0;
    #pragma unroll
    for (int seg = 0; seg < 9; seg++) {
        const int zz = cz - 1 + seg / 3;
        const int yy = cy - 1 + seg % 3;
        const bool val = (unsigned)zz < (unsigned)NCZ && (unsigned)yy < (unsigned)NCY;
        const int base = val ? (zz * NCY + yy) * NCX : 0;
        const int s = s_start[base + x0];
        const int e = val ? s_start[base + x1 + 1] : s;
        dlt[seg] = s - o[seg];
        o[seg + 1] = o[seg] + (e - s);
    }
}

// Branchless map: flat position k -> sorted-array index
__device__ __forceinline__ int sel_idx(int k, const int o[10], const int dlt[9]) {
    int d = dlt[0];
    #pragma unroll
    for (int i = 1; i < 9; i++)
        d = (k >= o[i]) ? dlt[i] : d;
    return k + d;
}

__global__ void __launch_bounds__(TPB, 4)
fused_kernel(const float* __restrict__ pos,
             float* __restrict__ out_idx,    // [NPTS, MAXN] float32
             float* __restrict__ out_cell,   // [NPTS, MAXN, 3] float32 (zeros)
             int* __restrict__ out_max)      // float32 bits, int atomicMax
{
    __shared__ unsigned bits[WPB][2][NPTS / 32];   // 16KB
    __shared__ int s_start[NCELLS + 1];            // 8.2KB block-local offsets
    __shared__ int wsum[8];

    const int tid  = threadIdx.x;
    const int warp = tid >> 5;
    const int lane = tid & 31;
    const int gi   = blockIdx.x * TPB + tid;

    // ---- phase 1: histogram (first 8192 threads own one point each) ----
    float px = 0.f, py = 0.f, pzz = 0.f;
    int c = 0, rank = 0;
    const bool own = gi < NPTS;
    if (own) {
        px  = pos[3 * gi + 0];
        py  = pos[3 * gi + 1];
        pzz = pos[3 * gi + 2];
        c = (binf(pzz, NCZ) * NCY + binf(py, NCY)) * NCX + binf(px, NCX);
        if (gi == 0) *out_max = 0;                 // 0x0 == 0.0f
        rank = atomicAdd(&g_count[c], 1);
    }

    // flat zeroing of cell_indices (12MB) across all threads
    {
        float4* cp = (float4*)out_cell;
        const float4 z4 = make_float4(0.f, 0.f, 0.f, 0.f);
        #pragma unroll
        for (int t = 0; t < 6; t++)
            cp[(size_t)t * (NB * TPB) + gi] = z4;
    }

    grid_barrier(NB);                              // histogram complete

    // ---- phase 2: block-local scan of 2048 bins, low register footprint ----
    {
        // pass 1: per-thread sum of its 8 bins (4 live at a time)
        int s = 0;
        #pragma unroll
        for (int t = 0; t < 8; t++) s += g_count[8 * tid + t];
        int v = s;
        #pragma unroll
        for (int d = 1; d < 32; d <<= 1) {
            const int u = __shfl_up_sync(0xffffffffu, v, d);
            if (lane >= d) v += u;
        }
        if (lane == 31) wsum[warp] = v;
        __syncthreads();
        if (warp == 0 && lane < 8) {
            int w = wsum[lane];
            #pragma unroll
            for (int d = 1; d < 8; d <<= 1) {
                const int u = __shfl_up_sync(0xffu, w, d);
                if (lane >= d) w += u;
            }
            wsum[lane] = w;
        }
        __syncthreads();
        // pass 2: re-read bins, emit running exclusive offsets
        int excl = v - s + (warp > 0 ? wsum[warp - 1] : 0);
        #pragma unroll
        for (int t = 0; t < 8; t++) {
            const int b = g_count[8 * tid + t];
            s_start[8 * tid + t] = excl;
            excl += b;
        }
        if (tid == TPB - 1) s_start[NCELLS] = excl;
    }
    __syncthreads();

    // ---- phase 3: cursor-free scatter ----
    if (own)
        g_spos[s_start[c] + rank] = make_float4(px, py, pzz, __int_as_float(gi));

    grid_barrier(NB);                              // sorted array ready

    // reset histogram for the next graph replay
    if (gi < NCELLS) g_count[gi] = 0;

    // ---- phase 4: neighbor search, warp per PAIR ----
    const int s0 = (blockIdx.x * WPB + warp) * 2;

    #pragma unroll
    for (int t = 0; t < 8; t++) {
        bits[warp][0][t * 32 + lane] = 0u;
        bits[warp][1][t * 32 + lane] = 0u;
    }

    const float4 A = g_spos[s0];
    const float4 B = g_spos[s0 + 1];
    const int rowA = __float_as_int(A.w);
    const int rowB = __float_as_int(B.w);

    const int ax = binf(A.x, NCX), bx = binf(B.x, NCX);
    const int ay = binf(A.y, NCY), by = binf(B.y, NCY);
    const int az = binf(A.z, NCZ), bz = binf(B.z, NCZ);
    __syncwarp();

    if (ay == by && az == bz) {
        // fast path: pair shares the (y,z) cell -> one window, union fine-x
        const int x0 = max(min(ax, bx) - 4, 0);
        const int x1 = min(max(ax, bx) + 4, NCX - 1);
        int o[10], dlt[9];
        make_window(s_start, x0, x1, ay, az, o, dlt);
        const int T = o[9];
        #pragma unroll 4
        for (int k = lane; k < T; k += 32) {
            const float4 q = g_spos[sel_idx(k, o, dlt)];
            const int j = __float_as_int(q.w);
            // exact left-to-right f32, no FMA (bit-matches reference)
            const float axd = __fsub_rn(q.x, A.x);
            const float ayd = __fsub_rn(q.y, A.y);
            const float azd = __fsub_rn(q.z, A.z);
            const float dA = __fadd_rn(__fadd_rn(__fmul_rn(axd, axd),
                                                 __fmul_rn(ayd, ayd)),
                                       __fmul_rn(azd, azd));
            const float bxd = __fsub_rn(q.x, B.x);
            const float byd = __fsub_rn(q.y, B.y);
            const float bzd = __fsub_rn(q.z, B.z);
            const float dB = __fadd_rn(__fadd_rn(__fmul_rn(bxd, bxd),
                                                 __fmul_rn(byd, byd)),
                                       __fmul_rn(bzd, bzd));
            if (dA <= CUT2 && j != rowA)
                atomicOr(&bits[warp][0][j >> 5], 1u << (j & 31));
            if (dB <= CUT2 && j != rowB)
                atomicOr(&bits[warp][1][j >> 5], 1u << (j & 31));
        }
    } else {
        // rare: independent full pass per row (each exactly covers its 3x3)
        #pragma unroll
        for (int r = 0; r < 2; r++) {
            const float4 P = r ? B : A;
            const int row = r ? rowB : rowA;
            const int cx = r ? bx : ax;
            const int x0 = max(cx - 4, 0);
            const int x1 = min(cx + 4, NCX - 1);
            int o[10], dlt[9];
            make_window(s_start, x0, x1, r ? by : ay, r ? bz : az, o, dlt);
            const int T = o[9];
            for (int k = lane; k < T; k += 32) {
                const float4 q = g_spos[sel_idx(k, o, dlt)];
                const int j = __float_as_int(q.w);
                const float dx = __fsub_rn(q.x, P.x);
                const float dy = __fsub_rn(q.y, P.y);
                const float dz = __fsub_rn(q.z, P.z);
                const float d2 = __fadd_rn(__fadd_rn(__fmul_rn(dx, dx),
                                                     __fmul_rn(dy, dy)),
                                           __fmul_rn(dz, dz));
                if (d2 <= CUT2 && j != row)
                    atomicOr(&bits[warp][r][j >> 5], 1u << (j & 31));
            }
        }
    }
    __syncwarp();

    // ---- ordered emission per row; 1 global atomicMax per warp ----
    int maxtot = 0;
    #pragma unroll
    for (int r = 0; r < 2; r++) {
        const int row = r ? rowB : rowA;
        unsigned myw[8];
        int csum = 0;
        #pragma unroll
        for (int t = 0; t < 8; t++) {
            myw[t] = bits[warp][r][lane * 8 + t];
            csum += __popc(myw[t]);
        }
        int x = csum;
        #pragma unroll
        for (int d = 1; d < 32; d <<= 1) {
            const int v = __shfl_up_sync(0xffffffffu, x, d);
            if (lane >= d) x += v;
        }
        int off = x - csum;
        const int total = __shfl_sync(0xffffffffu, x, 31);
        maxtot = max(maxtot, total);

        float* rowp = out_idx + (size_t)row * MAXN;
        #pragma unroll
        for (int t = 0; t < 8; t++) {
            unsigned m = myw[t];
            const int base = (lane * 8 + t) * 32;
            while (m) {
                const int b = __ffs(m) - 1;
                m &= m - 1;
                if (off < MAXN) rowp[off] = (float)(base + b);
                off++;
            }
        }
        const int st = total < MAXN ? total : MAXN;
        for (int k = st + lane; k < MAXN; k += 32)
            rowp[k] = -1.0f;
    }
    if (lane == 0) atomicMax(out_max, __float_as_int((float)maxtot));
}

extern "C" void kernel_launch(void* const* d_in, const int* in_sizes, int n_in,
                              void* d_out, int out_size)
{
    const float* pos = (const float*)d_in[0];
    float* out = (float*)d_out;

    const size_t toidx_elems = (size_t)NPTS * MAXN;      // 1,048,576
    const size_t cell_elems  = (size_t)NPTS * MAXN * 3;  // 3,145,728
    int* out_max = (int*)(out + toidx_elems + cell_elems);

    fused_kernel<<<NB, TPB>>>(pos, out, out + toidx_elems, out_max);
}

// round 14
// speedup vs baseline: 1.2304x; 1.2304x over previous
#include <cuda_runtime.h>
#include <cuda_bf16.h>

#define NPTS 8192
#define MAXN 128
#define NC 8
#define NCELLS 512          // 8^3
#define CUT2 0.015625f      // 0.125^2, exact in fp32
#define WPB 8               // warps per block; 2 rows per warp
#define TPB (WPB * 32)      // 256
#define NB (NPTS / (2 * WPB))  // 512 blocks, co-resident (<= 148*4)

// Scratch (no allocations allowed). Zero-initialized at module load.
__device__ int      g_count[NCELLS];   // histogram; reset in-kernel each run
__device__ float4   g_spos[NPTS];      // cell-sorted {x,y,z, idx-as-float-bits}
__device__ unsigned g_bar;             // monotonic grid-barrier ticket

__device__ __forceinline__ int cell_x(float v) {
    // v in [0,1): v*8 is an exact exponent shift in fp32; trunc == floor.
    int c = (int)(v * 8.0f);
    return c < 0 ? 0 : (c > 7 ? 7 : c);
}

// Grid barrier for a co-resident grid of nb blocks. Monotonic ticket ->
// counter is a multiple of nb at rest -> safe across graph replays.
__device__ __forceinline__ void grid_barrier(unsigned nb) {
    __syncthreads();
    if (threadIdx.x == 0) {
        __threadfence();
        const unsigned ticket = atomicAdd(&g_bar, 1u);
        const unsigned target = (ticket / nb + 1u) * nb;
        volatile unsigned* p = &g_bar;
        while (*p < target) { __nanosleep(32); }
    }
    __syncthreads();
}

// Build the 9-segment window (registers only; fully unrolled)
__device__ __forceinline__ void make_window(const int* __restrict__ s_start,
                                            int cx, int cy, int cz,
                                            int o[10], int dlt[9]) {
    const int cx0 = cx > 0 ? cx - 1 : 0;
    const int cx1 = cx < 7 ? cx + 1 : 7;
    o[0] = 0;
    #pragma unroll
    for (int seg = 0; seg < 9; seg++) {
        const int zz = cz - 1 + seg / 3;
        const int yy = cy - 1 + seg % 3;
        const bool val = (unsigned)zz < 8u && (unsigned)yy < 8u;
        const int base = val ? (zz * NC + yy) * NC : 0;
        const int s = s_start[base + cx0];
        const int e = val ? s_start[base + cx1 + 1] : s;
        dlt[seg] = s - o[seg];
        o[seg + 1] = o[seg] + (e - s);
    }
}

// Branchless map: flat position k -> sorted-array index
__device__ __forceinline__ int sel_idx(int k, const int o[10], const int dlt[9]) {
    int d = dlt[0];
    #pragma unroll
    for (int i = 1; i < 9; i++)
        d = (k >= o[i]) ? dlt[i] : d;
    return k + d;
}

__global__ void __launch_bounds__(TPB, 4)
fused_kernel(const float* __restrict__ pos,
             float* __restrict__ out_idx,    // [NPTS, MAXN] float32
             float* __restrict__ out_cell,   // [NPTS, MAXN, 3] float32 (zeros)
             int* __restrict__ out_max)      // float32 bits, int atomicMax
{
    __shared__ unsigned bits[WPB][2][NPTS / 32];   // 16KB
    __shared__ int s_start[NCELLS + 1];            // block-local cell offsets
    __shared__ int wsum[8];

    const int tid  = threadIdx.x;
    const int warp = tid >> 5;
    const int lane = tid & 31;
    const int gi   = blockIdx.x * TPB + tid;

    // ---- phase 1: histogram (first 8192 threads own one point each) ----
    float px = 0.f, py = 0.f, pzz = 0.f;
    int c = 0, rank = 0;
    const bool own = gi < NPTS;
    if (own) {
        px  = pos[3 * gi + 0];
        py  = pos[3 * gi + 1];
        pzz = pos[3 * gi + 2];
        c = (cell_x(pzz) * NC + cell_x(py)) * NC + cell_x(px);
        if (gi == 0) *out_max = 0;                 // 0x0 == 0.0f
        rank = atomicAdd(&g_count[c], 1);
    }

    // flat zeroing of cell_indices (12MB) across all threads
    {
        float4* cp = (float4*)out_cell;
        const float4 z4 = make_float4(0.f, 0.f, 0.f, 0.f);
        #pragma unroll
        for (int t = 0; t < 6; t++)
            cp[(size_t)t * (NB * TPB) + gi] = z4;
    }

    grid_barrier(NB);                              // histogram complete

    // ---- phase 2: redundant block-local scan of 512 cells (2 per thread) ----
    {
        const int c0 = g_count[2 * tid];
        const int c1 = g_count[2 * tid + 1];
        const int s  = c0 + c1;
        int v = s;
        #pragma unroll
        for (int d = 1; d < 32; d <<= 1) {
            const int u = __shfl_up_sync(0xffffffffu, v, d);
            if (lane >= d) v += u;
        }
        if (lane == 31) wsum[warp] = v;
        __syncthreads();
        if (warp == 0 && lane < 8) {
            int w = wsum[lane];
            #pragma unroll
            for (int d = 1; d < 8; d <<= 1) {
                const int u = __shfl_up_sync(0xffu, w, d);
                if (lane >= d) w += u;
            }
            wsum[lane] = w;
        }
        __syncthreads();
        const int incl = v + (warp > 0 ? wsum[warp - 1] : 0);
        const int excl = incl - s;
        s_start[2 * tid]     = excl;
        s_start[2 * tid + 1] = excl + c0;
        if (tid == TPB - 1) s_start[NCELLS] = incl;
    }
    __syncthreads();

    // ---- phase 3: cursor-free scatter ----
    if (own)
        g_spos[s_start[c] + rank] = make_float4(px, py, pzz, __int_as_float(gi));

    grid_barrier(NB);                              // sorted array ready

    // reset histogram for the next graph replay
    if (gi < NCELLS) g_count[gi] = 0;

    // ---- phase 4: neighbor search, warp per PAIR, flat selected loop ----
    const int s0 = (blockIdx.x * WPB + warp) * 2;

    // zero both bitsets with 128-bit stores (2KB per warp -> 4 STS.128/lane)
    {
        uint4* bz = (uint4*)&bits[warp][0][0];
        const uint4 z4 = make_uint4(0u, 0u, 0u, 0u);
        #pragma unroll
        for (int t = 0; t < 4; t++)
            bz[t * 32 + lane] = z4;
    }

    const float4 A = g_spos[s0];
    const float4 B = g_spos[s0 + 1];
    const int rowA = __float_as_int(A.w);
    const int rowB = __float_as_int(B.w);

    const int cax = cell_x(A.x), cay = cell_x(A.y), caz = cell_x(A.z);
    const int cbx = cell_x(B.x), cby = cell_x(B.y), cbz = cell_x(B.z);
    __syncwarp();

    if (cax == cbx && cay == cby && caz == cbz) {
        int o[10], dlt[9];
        make_window(s_start, cax, cay, caz, o, dlt);
        const int T = o[9];
        #pragma unroll 8
        for (int k = lane; k < T; k += 32) {
            const float4 q = g_spos[sel_idx(k, o, dlt)];
            const int j = __float_as_int(q.w);
            // exact left-to-right f32, no FMA (bit-matches reference)
            const float axd = __fsub_rn(q.x, A.x);
            const float ayd = __fsub_rn(q.y, A.y);
            const float azd = __fsub_rn(q.z, A.z);
            const float dA = __fadd_rn(__fadd_rn(__fmul_rn(axd, axd),
                                                 __fmul_rn(ayd, ayd)),
                                       __fmul_rn(azd, azd));
            const float bxd = __fsub_rn(q.x, B.x);
            const float byd = __fsub_rn(q.y, B.y);
            const float bzd = __fsub_rn(q.z, B.z);
            const float dB = __fadd_rn(__fadd_rn(__fmul_rn(bxd, bxd),
                                                 __fmul_rn(byd, byd)),
                                       __fmul_rn(bzd, bzd));
            if (dA <= CUT2 && j != rowA)
                atomicOr(&bits[warp][0][j >> 5], 1u << (j & 31));
            if (dB <= CUT2 && j != rowB)
                atomicOr(&bits[warp][1][j >> 5], 1u << (j & 31));
        }
    } else {
        // rare (~6%): two flat passes, one per row
        #pragma unroll
        for (int r = 0; r < 2; r++) {
            const float4 P = r ? B : A;
            const int row = r ? rowB : rowA;
            int o[10], dlt[9];
            make_window(s_start,
                        r ? cbx : cax, r ? cby : cay, r ? cbz : caz, o, dlt);
            const int T = o[9];
            #pragma unroll 4
            for (int k = lane; k < T; k += 32) {
                const float4 q = g_spos[sel_idx(k, o, dlt)];
                const int j = __float_as_int(q.w);
                const float dx = __fsub_rn(q.x, P.x);
                const float dy = __fsub_rn(q.y, P.y);
                const float dz = __fsub_rn(q.z, P.z);
                const float d2 = __fadd_rn(__fadd_rn(__fmul_rn(dx, dx),
                                                     __fmul_rn(dy, dy)),
                                           __fmul_rn(dz, dz));
                if (d2 <= CUT2 && j != row)
                    atomicOr(&bits[warp][r][j >> 5], 1u << (j & 31));
            }
        }
    }
    __syncwarp();

    // ---- ordered emission per row; 1 global atomicMax per warp ----
    int maxtot = 0;
    #pragma unroll
    for (int r = 0; r < 2; r++) {
        const int row = r ? rowB : rowA;
        unsigned myw[8];
        int csum = 0;
        #pragma unroll
        for (int t = 0; t < 8; t++) {
            myw[t] = bits[warp][r][lane * 8 + t];
            csum += __popc(myw[t]);
        }
        int x = csum;
        #pragma unroll
        for (int d = 1; d < 32; d <<= 1) {
            const int v = __shfl_up_sync(0xffffffffu, x, d);
            if (lane >= d) x += v;
        }
        int off = x - csum;
        const int total = __shfl_sync(0xffffffffu, x, 31);
        maxtot = max(maxtot, total);

        float* rowp = out_idx + (size_t)row * MAXN;
        #pragma unroll
        for (int t = 0; t < 8; t++) {
            unsigned m = myw[t];
            const int base = (lane * 8 + t) * 32;
            while (m) {
                const int b = __ffs(m) - 1;
                m &= m - 1;
                if (off < MAXN) rowp[off] = (float)(base + b);
                off++;
            }
        }
        const int st = total < MAXN ? total : MAXN;
        for (int k = st + lane; k < MAXN; k += 32)
            rowp[k] = -1.0f;
    }
    if (lane == 0) atomicMax(out_max, __float_as_int((float)maxtot));
}

extern "C" void kernel_launch(void* const* d_in, const int* in_sizes, int n_in,
                              void* d_out, int out_size)
{
    const float* pos = (const float*)d_in[0];
    float* out = (float*)d_out;

    const size_t toidx_elems = (size_t)NPTS * MAXN;      // 1,048,576
    const size_t cell_elems  = (size_t)NPTS * MAXN * 3;  // 3,145,728
    int* out_max = (int*)(out + toidx_elems + cell_elems);

    fused_kernel<<<NB, TPB>>>(pos, out, out + toidx_elems, out_max);
}